// round 5
// baseline (speedup 1.0000x reference)
#include <cuda_runtime.h>
#include <cstdint>

#define BATCH 16384
#define DIM   1024
#define TT    128
#define BM    128                    // batch rows per CTA
#define NCTA  (BATCH/BM)             // 128
#define THREADS 512
#define KC    32                     // K per chunk
#define NCHUNK (DIM/KC)              // 32
#define NSTAGE 3
#define ROWB  160                    // B row stride (bytes): 32 floats + 32B pad
#define BSTAGE (128*ROWB)            // 20480
#define LSTR  130                    // logits row stride (floats)
#define LOGIT_BYTES (128*LSTR*4)     // 66560
#define MISC_OFF LOGIT_BYTES
#define SMEM_DYN (MISC_OFF + 1024)

__device__ float g_partials[NCTA];
__device__ unsigned int g_done = 0;   // self-resets via atomicInc wrap

// ---------------- PTX helpers ----------------
__device__ __forceinline__ uint32_t smem_u32(const void* p) {
    uint32_t a;
    asm("{ .reg .u64 t; cvta.to.shared.u64 t, %1; cvt.u32.u64 %0, t; }"
        : "=r"(a) : "l"(p));
    return a;
}
__device__ __forceinline__ void cp_async16(uint32_t saddr, const void* gaddr) {
    asm volatile("cp.async.cg.shared.global [%0], [%1], 16;"
                 :: "r"(saddr), "l"(gaddr) : "memory");
}
template <int IMM>
__device__ __forceinline__ uint2 lds64(uint32_t base) {
    uint2 v;
    asm volatile("ld.shared.v2.b32 {%0,%1}, [%2+%3];"
                 : "=r"(v.x), "=r"(v.y) : "r"(base), "n"(IMM));
    return v;
}
// raw f32 bits as tf32 operands: HW truncates low mantissa bits
__device__ __forceinline__ void mma_tf32(float d[4],
                                         uint32_t a0, uint32_t a1, uint32_t a2, uint32_t a3,
                                         uint32_t b0, uint32_t b1) {
    asm volatile(
        "mma.sync.aligned.m16n8k8.row.col.f32.tf32.tf32.f32 "
        "{%0,%1,%2,%3}, {%4,%5,%6,%7}, {%8,%9}, {%0,%1,%2,%3};"
        : "+f"(d[0]), "+f"(d[1]), "+f"(d[2]), "+f"(d[3])
        : "r"(a0), "r"(a1), "r"(a2), "r"(a3), "r"(b0), "r"(b1));
}

// ---------------- fused kernel ----------------
__global__ __launch_bounds__(THREADS, 1)
void qrl_mma_kernel(const float* __restrict__ X,     // [B, D]
                    const float* __restrict__ W,     // [T, D]
                    const float* __restrict__ bias,  // [T]
                    const int*   __restrict__ di,    // [B, 12]
                    const int*   __restrict__ dm,    // [B, 12]
                    float* __restrict__ out)
{
    extern __shared__ __align__(128) char smem[];
    float* ls    = (float*)smem;                     // logits alias stage buffers post-GEMM
    float* sbias = (float*)(smem + MISC_OFF);        // 128 floats
    float* sred  = (float*)(smem + MISC_OFF + 512);  // 16 floats
    int*   sflag = (int*)  (smem + MISC_OFF + 640);

    const uint32_t sbase = smem_u32(smem);
    const int tid  = threadIdx.x;
    const int wid  = tid >> 5;
    const int lane = tid & 31;
    const int bid  = blockIdx.x;
    const int row0 = bid * BM;

    const int wm = wid >> 1;       // 8 groups of 16 rows
    const int wn = wid & 1;        // 2 groups of 64 cols
    const int g  = lane >> 2;      // 0..7
    const int c  = lane & 3;       // 0..3

    if (tid < TT) sbias[tid] = bias[tid];

    // A straight from gmem: rows wm*16+g and +8, k-pair 2c..2c+1 (8B)
    const float* pa0 = X + (size_t)(row0 + wm * 16 + g) * DIM + c * 2;
    const float* pa1 = pa0 + 8 * DIM;
    // B fragment base in smem (per-stage offset added in loop)
    const uint32_t boff = (uint32_t)((wn * 64 + g) * ROWB + c * 8);

    // ---- B chunk loader: 512 thr x 2 x 16B = 16KB ----
    auto load_chunk = [&](int kc, int st) {
        const uint32_t sa = sbase + st * BSTAGE;
        #pragma unroll
        for (int i = 0; i < 2; ++i) {
            int u = tid + THREADS * i;     // 0..1023
            int r = u >> 3, s = u & 7;
            cp_async16(sa + r * ROWB + s * 16, W + (size_t)r * DIM + kc * KC + s * 4);
        }
        asm volatile("cp.async.commit_group;" ::: "memory");
    };

    float acc[8][4];
    #pragma unroll
    for (int j = 0; j < 8; ++j)
        #pragma unroll
        for (int q = 0; q < 4; ++q) acc[j][q] = 0.f;

    uint2 Ab[2][4][2];   // [buf][kstep][row g / g+8]

    // prologue: A chunk 0, B chunks 0 & 1
    #pragma unroll
    for (int ks = 0; ks < 4; ++ks) {
        Ab[0][ks][0] = *(const uint2*)(pa0 + ks * 8);
        Ab[0][ks][1] = *(const uint2*)(pa1 + ks * 8);
    }
    load_chunk(0, 0);
    load_chunk(1, 1);

    #pragma unroll 2
    for (int kc = 0; kc < NCHUNK; ++kc) {
        const int pb = kc & 1;
        // prefetch next chunk's A into the other reg buffer (overlaps wait+barrier)
        if (kc + 1 < NCHUNK) {
            const float* qa0 = pa0 + (kc + 1) * KC;
            const float* qa1 = pa1 + (kc + 1) * KC;
            #pragma unroll
            for (int ks = 0; ks < 4; ++ks) {
                Ab[pb ^ 1][ks][0] = *(const uint2*)(qa0 + ks * 8);
                Ab[pb ^ 1][ks][1] = *(const uint2*)(qa1 + ks * 8);
            }
        }
        if (kc < NCHUNK - 2) asm volatile("cp.async.wait_group 1;" ::: "memory");
        else                 asm volatile("cp.async.wait_group 0;" ::: "memory");
        __syncthreads();
        if (kc + 2 < NCHUNK) load_chunk(kc + 2, (kc + 2) % NSTAGE);

        const uint32_t aB = sbase + (kc % NSTAGE) * BSTAGE + boff;

        #pragma unroll
        for (int ks = 0; ks < 4; ++ks) {
            const uint2 A0 = Ab[pb][ks][0];
            const uint2 A1 = Ab[pb][ks][1];
            #define BMMA(J) do {                                                  \
                uint2 Bj = lds64<(J) * 8 * ROWB>(aB + ks * 32);                    \
                mma_tf32(acc[J], A0.x, A1.x, A0.y, A1.y, Bj.x, Bj.y);              \
            } while (0)
            BMMA(0); BMMA(1); BMMA(2); BMMA(3);
            BMMA(4); BMMA(5); BMMA(6); BMMA(7);
            #undef BMMA
        }
    }

    // ---- write logits to smem (alias stage buffers) ----
    __syncthreads();
    {
        const int r0 = wm * 16 + g;
        #pragma unroll
        for (int j = 0; j < 8; ++j) {
            const int c0 = wn * 64 + j * 8 + 2 * c;
            *(float2*)&ls[(size_t)r0 * LSTR + c0]       = make_float2(acc[j][0], acc[j][1]);
            *(float2*)&ls[(size_t)(r0 + 8) * LSTR + c0] = make_float2(acc[j][2], acc[j][3]);
        }
    }
    __syncthreads();

    // ---- softmax + gather: 4 lanes per row ----
    const int r = tid >> 2;
    const int q = tid & 3;
    const float* lr = &ls[(size_t)r * LSTR];

    float mx = -3.0e38f;
    #pragma unroll
    for (int i = 0; i < 32; ++i) {
        int cc = q + 4 * i;
        mx = fmaxf(mx, lr[cc] + sbias[cc]);
    }
    mx = fmaxf(mx, __shfl_xor_sync(0xffffffffu, mx, 1));
    mx = fmaxf(mx, __shfl_xor_sync(0xffffffffu, mx, 2));

    float se = 0.f;
    #pragma unroll
    for (int i = 0; i < 32; ++i) {
        int cc = q + 4 * i;
        se += __expf(lr[cc] + sbias[cc] - mx);
    }
    se += __shfl_xor_sync(0xffffffffu, se, 1);
    se += __shfl_xor_sync(0xffffffffu, se, 2);

    float gg = 0.f;
    const int* dip = di + (size_t)(row0 + r) * 12;
    const int* dmp = dm + (size_t)(row0 + r) * 12;
    #pragma unroll
    for (int j = q; j < 12; j += 4) {
        int idx = dip[j];
        if (dmp[j]) gg += __expf(lr[idx] + sbias[idx] - mx);
    }
    gg += __shfl_xor_sync(0xffffffffu, gg, 1);
    gg += __shfl_xor_sync(0xffffffffu, gg, 2);

    float part = (q == 0) ? (gg / se) : 0.f;

    // deterministic block reduce (16 warps)
    #pragma unroll
    for (int o = 16; o; o >>= 1) part += __shfl_down_sync(0xffffffffu, part, o);
    if (lane == 0) sred[wid] = part;
    __syncthreads();
    if (tid == 0) {
        float s = 0.f;
        #pragma unroll
        for (int i = 0; i < 16; ++i) s += sred[i];
        g_partials[bid] = s;
        __threadfence();
        unsigned old = atomicInc(&g_done, NCTA - 1);   // wraps to 0: replay-safe
        sflag[0] = (old == NCTA - 1) ? 1 : 0;
    }
    __syncthreads();

    // ---- fused finalize: last CTA reduces all partials ----
    if (sflag[0] && tid < NCTA) {
        __threadfence();
        float v = g_partials[tid];
        #pragma unroll
        for (int o = 16; o; o >>= 1) v += __shfl_down_sync(0xffffffffu, v, o);
        if (lane == 0) sred[wid] = v;
        __syncwarp();
        if (tid == 0) {
            float s = ((sred[0] + sred[1]) + (sred[2] + sred[3]));
            out[0] = s * (1.0f / 65536.f);   // / (B * V)
        }
    }
}

extern "C" void kernel_launch(void* const* d_in, const int* in_sizes, int n_in,
                              void* d_out, int out_size) {
    const float* X  = (const float*)d_in[0];
    const float* W  = (const float*)d_in[1];
    const float* b  = (const float*)d_in[2];
    const int*   di = (const int*)d_in[3];
    const int*   dm = (const int*)d_in[4];

    cudaFuncSetAttribute(qrl_mma_kernel,
                         cudaFuncAttributeMaxDynamicSharedMemorySize, SMEM_DYN);
    qrl_mma_kernel<<<NCTA, THREADS, SMEM_DYN>>>(X, W, b, di, dm, (float*)d_out);
}

// round 7
// speedup vs baseline: 1.2645x; 1.2645x over previous
#include <cuda_runtime.h>
#include <cuda_fp16.h>
#include <cstdint>

#define BATCH 16384
#define DIM   1024
#define TT    128
#define BM    128
#define NCTA  128
#define THREADS 512
#define KC    32
#define NCHUNK 32
#define NSTAGE 3
#define ABYTES 8192                  // 128 rows x 64B (f16)
#define STAGE_BYTES 16384            // A + B
#define LSTR  130
#define LOGIT_BYTES (128*LSTR*4)     // 66560
#define MISC_OFF LOGIT_BYTES
#define SMEM_DYN (MISC_OFF + 1024)

__device__ float g_partials[NCTA];
__device__ unsigned int g_done = 0;   // self-resets via atomicInc wrap

// ---------------- PTX helpers ----------------
__device__ __forceinline__ uint32_t smem_u32(const void* p) {
    uint32_t a;
    asm("{ .reg .u64 t; cvta.to.shared.u64 t, %1; cvt.u32.u64 %0, t; }"
        : "=r"(a) : "l"(p));
    return a;
}
template <int IMM>
__device__ __forceinline__ uint4 lds128(uint32_t base) {
    uint4 v;
    asm volatile("ld.shared.v4.b32 {%0,%1,%2,%3}, [%4+%5];"
                 : "=r"(v.x), "=r"(v.y), "=r"(v.z), "=r"(v.w)
                 : "r"(base), "n"(IMM));
    return v;
}
__device__ __forceinline__ void sts128(uint32_t addr, uint4 v) {
    asm volatile("st.shared.v4.b32 [%0], {%1,%2,%3,%4};"
                 :: "r"(addr), "r"(v.x), "r"(v.y), "r"(v.z), "r"(v.w) : "memory");
}
__device__ __forceinline__ uint32_t f2h2(float x, float y) {
    __half2 h = __floats2half2_rn(x, y);
    return *(uint32_t*)&h;
}
__device__ __forceinline__ void mma_f16(float d[4],
                                        uint32_t a0, uint32_t a1, uint32_t a2, uint32_t a3,
                                        uint32_t b0, uint32_t b1) {
    asm volatile(
        "mma.sync.aligned.m16n8k16.row.col.f32.f16.f16.f32 "
        "{%0,%1,%2,%3}, {%4,%5,%6,%7}, {%8,%9}, {%0,%1,%2,%3};"
        : "+f"(d[0]), "+f"(d[1]), "+f"(d[2]), "+f"(d[3])
        : "r"(a0), "r"(a1), "r"(a2), "r"(a3), "r"(b0), "r"(b1));
}

// ---------------- fused kernel ----------------
__global__ __launch_bounds__(THREADS, 1)
void qrl_h16_kernel(const float* __restrict__ X,     // [B, D]
                    const float* __restrict__ W,     // [T, D]
                    const float* __restrict__ bias,  // [T]
                    const int*   __restrict__ di,    // [B, 12]
                    const int*   __restrict__ dm,    // [B, 12]
                    float* __restrict__ out)
{
    extern __shared__ __align__(128) char smem[];
    float* ls    = (float*)smem;                     // logits alias stage buffers post-GEMM
    float* sbias = (float*)(smem + MISC_OFF);        // 128 floats
    float* sred  = (float*)(smem + MISC_OFF + 512);  // 16 floats
    int*   sflag = (int*)  (smem + MISC_OFF + 640);

    const uint32_t sbase = smem_u32(smem);
    const int tid  = threadIdx.x;
    const int wid  = tid >> 5;
    const int lane = tid & 31;
    const int bid  = blockIdx.x;
    const int row0 = bid * BM;

    const int wm = wid & 3;        // 4 m-groups of 32 rows
    const int wn = wid >> 2;       // 4 n-groups of 32 cols
    const int g  = lane >> 2;      // 0..7
    const int c  = lane & 3;       // 0..3

    if (tid < TT) sbias[tid] = bias[tid];

    // fragment bases (64B rows, bit-5 XOR swizzle: off ^= (row&2)<<4; row&2 == g&2 here)
    const uint32_t xr = (uint32_t)((c * 16) ^ ((g & 2) << 4));
    const uint32_t abase0 = (uint32_t)((wm * 32 + g) * 64) + xr;            // + stage
    const uint32_t bbase0 = (uint32_t)(ABYTES + (wn * 32 + g) * 64) + xr;   // + stage

    // ---- loader geometry: thread u -> row u>>2, 16B chunk u&3 ----
    const int ldr = tid >> 2;
    const int ldc = tid & 3;
    const uint32_t sts_off = (uint32_t)(ldr * 64 + ((ldc ^ (ldr & 2)) * 16));
    const float* xg = X + (size_t)(row0 + ldr) * DIM + ldc * 8;
    const float* wg = W + (size_t)ldr * DIM + ldc * 8;

    float4 rx0, rx1, rw0, rw1;
    auto ldg = [&](int kc) {
        const float* xp = xg + kc * KC;
        const float* wp = wg + kc * KC;
        rx0 = *(const float4*)xp; rx1 = *(const float4*)(xp + 4);
        rw0 = *(const float4*)wp; rw1 = *(const float4*)(wp + 4);
    };
    auto sts = [&](int st) {
        const uint32_t sa = sbase + st * STAGE_BYTES + sts_off;
        uint4 v;
        v.x = f2h2(rx0.x, rx0.y); v.y = f2h2(rx0.z, rx0.w);
        v.z = f2h2(rx1.x, rx1.y); v.w = f2h2(rx1.z, rx1.w);
        sts128(sa, v);
        v.x = f2h2(rw0.x, rw0.y); v.y = f2h2(rw0.z, rw0.w);
        v.z = f2h2(rw1.x, rw1.y); v.w = f2h2(rw1.z, rw1.w);
        sts128(sa + ABYTES, v);
    };

    float acc[2][4][4];
    #pragma unroll
    for (int m = 0; m < 2; ++m)
        #pragma unroll
        for (int n = 0; n < 4; ++n)
            #pragma unroll
            for (int q = 0; q < 4; ++q) acc[m][n][q] = 0.f;

    // prologue: chunk0 -> stage0; chunk1 in regs
    ldg(0); sts(0); ldg(1);

    for (int kc = 0; kc < NCHUNK; ++kc) {
        if (kc + 1 < NCHUNK) sts((kc + 1) % NSTAGE);
        if (kc + 2 < NCHUNK) ldg(kc + 2);
        __syncthreads();

        const uint32_t sa = sbase + (kc % NSTAGE) * STAGE_BYTES;
        const uint32_t aA = sa + abase0;
        const uint32_t aB = sa + bbase0;

        // one LDS.128 per row/col covers the whole 32-K chunk (both k16 steps)
        uint4 Af[2][2], Bf[4];
        Af[0][0] = lds128<0>(aA);         // rows wm*32+g
        Af[0][1] = lds128<512>(aA);       // +8
        Af[1][0] = lds128<1024>(aA);      // +16
        Af[1][1] = lds128<1536>(aA);      // +24
        Bf[0] = lds128<0>(aB);
        Bf[1] = lds128<512>(aB);
        Bf[2] = lds128<1024>(aB);
        Bf[3] = lds128<1536>(aB);

        // k16 step 0: regs .x (half0) .y (half1); step 1: .z .w
        #pragma unroll
        for (int m = 0; m < 2; ++m) {
            #pragma unroll
            for (int n = 0; n < 4; ++n) {
                mma_f16(acc[m][n], Af[m][0].x, Af[m][1].x, Af[m][0].y, Af[m][1].y,
                        Bf[n].x, Bf[n].y);
                mma_f16(acc[m][n], Af[m][0].z, Af[m][1].z, Af[m][0].w, Af[m][1].w,
                        Bf[n].z, Bf[n].w);
            }
        }
    }

    // ---- write logits to smem (alias stage buffers) ----
    __syncthreads();
    #pragma unroll
    for (int m = 0; m < 2; ++m) {
        const int r0 = wm * 32 + m * 16 + g;
        #pragma unroll
        for (int n = 0; n < 4; ++n) {
            const int c0 = wn * 32 + n * 8 + 2 * c;
            *(float2*)&ls[(size_t)r0 * LSTR + c0]       = make_float2(acc[m][n][0], acc[m][n][1]);
            *(float2*)&ls[(size_t)(r0 + 8) * LSTR + c0] = make_float2(acc[m][n][2], acc[m][n][3]);
        }
    }
    __syncthreads();

    // ---- softmax + gather: 4 lanes per row ----
    const int r = tid >> 2;
    const int q = tid & 3;
    const float* lr2 = &ls[(size_t)r * LSTR];

    float mx = -3.0e38f;
    #pragma unroll
    for (int i = 0; i < 32; ++i) {
        int cc = q + 4 * i;
        mx = fmaxf(mx, lr2[cc] + sbias[cc]);
    }
    mx = fmaxf(mx, __shfl_xor_sync(0xffffffffu, mx, 1));
    mx = fmaxf(mx, __shfl_xor_sync(0xffffffffu, mx, 2));

    float se = 0.f;
    #pragma unroll
    for (int i = 0; i < 32; ++i) {
        int cc = q + 4 * i;
        se += __expf(lr2[cc] + sbias[cc] - mx);
    }
    se += __shfl_xor_sync(0xffffffffu, se, 1);
    se += __shfl_xor_sync(0xffffffffu, se, 2);

    float gg = 0.f;
    const int* dip = di + (size_t)(row0 + r) * 12;
    const int* dmp = dm + (size_t)(row0 + r) * 12;
    #pragma unroll
    for (int j = q; j < 12; j += 4) {
        int idx = dip[j];
        if (dmp[j]) gg += __expf(lr2[idx] + sbias[idx] - mx);
    }
    gg += __shfl_xor_sync(0xffffffffu, gg, 1);
    gg += __shfl_xor_sync(0xffffffffu, gg, 2);

    float part = (q == 0) ? (gg / se) : 0.f;

    // deterministic block reduce (16 warps) -- sred writes/reads fenced by __syncthreads
    #pragma unroll
    for (int o = 16; o; o >>= 1) part += __shfl_down_sync(0xffffffffu, part, o);
    if (lane == 0) sred[wid] = part;
    __syncthreads();
    if (tid == 0) {
        float s = 0.f;
        #pragma unroll
        for (int i = 0; i < 16; ++i) s += sred[i];
        g_partials[bid] = s;
        __threadfence();
        unsigned old = atomicInc(&g_done, NCTA - 1);   // wraps to 0: replay-safe
        sflag[0] = (old == NCTA - 1) ? 1 : 0;
    }
    __syncthreads();

    // ---- fused finalize: WARP 0 of the last CTA only (no cross-warp smem) ----
    if (sflag[0] && wid == 0) {
        __threadfence();   // acquire all CTAs' g_partials
        float v = 0.f;
        #pragma unroll
        for (int i = 0; i < 4; ++i) v += g_partials[lane + 32 * i];
        #pragma unroll
        for (int o = 16; o; o >>= 1) v += __shfl_down_sync(0xffffffffu, v, o);
        if (lane == 0) out[0] = v * (1.0f / 65536.f);   // / (B * V)
    }
}

extern "C" void kernel_launch(void* const* d_in, const int* in_sizes, int n_in,
                              void* d_out, int out_size) {
    const float* X  = (const float*)d_in[0];
    const float* W  = (const float*)d_in[1];
    const float* b  = (const float*)d_in[2];
    const int*   di = (const int*)d_in[3];
    const int*   dm = (const int*)d_in[4];

    cudaFuncSetAttribute(qrl_h16_kernel,
                         cudaFuncAttributeMaxDynamicSharedMemorySize, SMEM_DYN);
    qrl_h16_kernel<<<NCTA, THREADS, SMEM_DYN>>>(X, W, b, di, dm, (float*)d_out);
}

// round 8
// speedup vs baseline: 1.2655x; 1.0009x over previous
#include <cuda_runtime.h>
#include <cuda_fp16.h>
#include <cstdint>

#define BATCH 16384
#define DIM   1024
#define TT    128
#define BM    64
#define NCTA  256
#define THREADS 256
#define KC    32
#define NCHUNK 32
#define NSTAGE 3
#define ABYTES 4096                  // 64 rows x 64B (f16)
#define STAGE_BYTES 12288            // A(4K) + B(8K)
#define LSTR  130
#define MISC_OFF (NSTAGE*STAGE_BYTES)   // 36864 (logits 64*130*4=33280 fit below)
#define SMEM_DYN (MISC_OFF + 1024)

__device__ float g_partials[NCTA];
__device__ unsigned int g_done = 0;   // self-resets via atomicInc wrap

// ---------------- PTX helpers ----------------
__device__ __forceinline__ uint32_t smem_u32(const void* p) {
    uint32_t a;
    asm("{ .reg .u64 t; cvta.to.shared.u64 t, %1; cvt.u32.u64 %0, t; }"
        : "=r"(a) : "l"(p));
    return a;
}
template <int IMM>
__device__ __forceinline__ uint4 lds128(uint32_t base) {
    uint4 v;
    asm volatile("ld.shared.v4.b32 {%0,%1,%2,%3}, [%4+%5];"
                 : "=r"(v.x), "=r"(v.y), "=r"(v.z), "=r"(v.w)
                 : "r"(base), "n"(IMM));
    return v;
}
__device__ __forceinline__ void sts128(uint32_t addr, uint4 v) {
    asm volatile("st.shared.v4.b32 [%0], {%1,%2,%3,%4};"
                 :: "r"(addr), "r"(v.x), "r"(v.y), "r"(v.z), "r"(v.w) : "memory");
}
__device__ __forceinline__ uint32_t f2h2(float x, float y) {
    __half2 h = __floats2half2_rn(x, y);
    return *(uint32_t*)&h;
}
__device__ __forceinline__ void mma_f16(float d[4],
                                        uint32_t a0, uint32_t a1, uint32_t a2, uint32_t a3,
                                        uint32_t b0, uint32_t b1) {
    asm volatile(
        "mma.sync.aligned.m16n8k16.row.col.f32.f16.f16.f32 "
        "{%0,%1,%2,%3}, {%4,%5,%6,%7}, {%8,%9}, {%0,%1,%2,%3};"
        : "+f"(d[0]), "+f"(d[1]), "+f"(d[2]), "+f"(d[3])
        : "r"(a0), "r"(a1), "r"(a2), "r"(a3), "r"(b0), "r"(b1));
}

// ---------------- fused kernel ----------------
__global__ __launch_bounds__(THREADS, 2)
void qrl_h16_kernel(const float* __restrict__ X,     // [B, D]
                    const float* __restrict__ W,     // [T, D]
                    const float* __restrict__ bias,  // [T]
                    const int*   __restrict__ di,    // [B, 12]
                    const int*   __restrict__ dm,    // [B, 12]
                    float* __restrict__ out)
{
    extern __shared__ __align__(128) char smem[];
    float* ls    = (float*)smem;                     // logits alias stage buffers post-GEMM
    float* sbias = (float*)(smem + MISC_OFF);        // 128 floats
    float* sred  = (float*)(smem + MISC_OFF + 512);  // 8 floats
    int*   sflag = (int*)  (smem + MISC_OFF + 576);

    const uint32_t sbase = smem_u32(smem);
    const int tid  = threadIdx.x;
    const int wid  = tid >> 5;
    const int lane = tid & 31;
    const int bid  = blockIdx.x;
    const int row0 = bid * BM;

    const int wm = wid & 1;        // 2 m-groups of 32 rows
    const int wn = wid >> 1;       // 4 n-groups of 32 cols
    const int g  = lane >> 2;      // 0..7
    const int c  = lane & 3;       // 0..3

    if (tid < TT) sbias[tid] = bias[tid];

    // fragment bases (64B rows, bit-5 XOR swizzle: off ^= (row&2)<<4; row&2 == g&2)
    const uint32_t xr = (uint32_t)((c * 16) ^ ((g & 2) << 4));
    const uint32_t abase0 = (uint32_t)((wm * 32 + g) * 64) + xr;
    const uint32_t bbase0 = (uint32_t)(ABYTES + (wn * 32 + g) * 64) + xr;

    // ---- loader geometry: thread u -> row u>>2, 16B f16 chunk u&3 ----
    const int ldr = tid >> 2;      // 0..63
    const int ldc = tid & 3;
    const uint32_t a_sts = (uint32_t)(ldr * 64 + ((ldc ^ (ldr & 2)) * 16));
    const float* xg  = X + (size_t)(row0 + ldr) * DIM + ldc * 8;
    const float* wg0 = W + (size_t)ldr * DIM + ldc * 8;          // B rows ldr, ldr+64

    float4 bx[2][2];     // [buf][2 float4] A source
    float4 bw[2][4];     // [buf][4 float4] B source (2 rows)
    auto ldg = [&](int kc, int b) {
        const float* xp = xg + kc * KC;
        bx[b][0] = *(const float4*)xp;  bx[b][1] = *(const float4*)(xp + 4);
        const float* wp = wg0 + kc * KC;
        bw[b][0] = *(const float4*)wp;  bw[b][1] = *(const float4*)(wp + 4);
        wp += (size_t)64 * DIM;
        bw[b][2] = *(const float4*)wp;  bw[b][3] = *(const float4*)(wp + 4);
    };
    auto sts = [&](int st, int b) {
        const uint32_t sa = sbase + st * STAGE_BYTES;
        uint4 v;
        v.x = f2h2(bx[b][0].x, bx[b][0].y); v.y = f2h2(bx[b][0].z, bx[b][0].w);
        v.z = f2h2(bx[b][1].x, bx[b][1].y); v.w = f2h2(bx[b][1].z, bx[b][1].w);
        sts128(sa + a_sts, v);
        v.x = f2h2(bw[b][0].x, bw[b][0].y); v.y = f2h2(bw[b][0].z, bw[b][0].w);
        v.z = f2h2(bw[b][1].x, bw[b][1].y); v.w = f2h2(bw[b][1].z, bw[b][1].w);
        sts128(sa + ABYTES + a_sts, v);
        v.x = f2h2(bw[b][2].x, bw[b][2].y); v.y = f2h2(bw[b][2].z, bw[b][2].w);
        v.z = f2h2(bw[b][3].x, bw[b][3].y); v.w = f2h2(bw[b][3].z, bw[b][3].w);
        sts128(sa + ABYTES + 4096 + a_sts, v);    // rows +64
    };

    float acc[2][4][4];
    #pragma unroll
    for (int m = 0; m < 2; ++m)
        #pragma unroll
        for (int n = 0; n < 4; ++n)
            #pragma unroll
            for (int q = 0; q < 4; ++q) acc[m][n][q] = 0.f;

    // prologue: chunk0 -> stage0 (buf0); chunk1 -> buf1
    ldg(0, 0); sts(0, 0); ldg(1, 1);

    for (int kc = 0; kc < NCHUNK; ++kc) {
        if (kc + 2 < NCHUNK) ldg(kc + 2, kc & 1);           // into buf freed last iter
        if (kc + 1 < NCHUNK) sts((kc + 1) % NSTAGE, (kc + 1) & 1);
        __syncthreads();

        const uint32_t sa = sbase + (kc % NSTAGE) * STAGE_BYTES;
        const uint32_t aA = sa + abase0;
        const uint32_t aB = sa + bbase0;

        // one LDS.128 per row/col covers the whole 32-K chunk (both k16 steps)
        uint4 Af[2][2], Bf[4];
        Af[0][0] = lds128<0>(aA);         // rows wm*32+g
        Af[0][1] = lds128<512>(aA);       // +8
        Af[1][0] = lds128<1024>(aA);      // +16
        Af[1][1] = lds128<1536>(aA);      // +24
        Bf[0] = lds128<0>(aB);
        Bf[1] = lds128<512>(aB);
        Bf[2] = lds128<1024>(aB);
        Bf[3] = lds128<1536>(aB);

        #pragma unroll
        for (int m = 0; m < 2; ++m) {
            #pragma unroll
            for (int n = 0; n < 4; ++n) {
                mma_f16(acc[m][n], Af[m][0].x, Af[m][1].x, Af[m][0].y, Af[m][1].y,
                        Bf[n].x, Bf[n].y);
                mma_f16(acc[m][n], Af[m][0].z, Af[m][1].z, Af[m][0].w, Af[m][1].w,
                        Bf[n].z, Bf[n].w);
            }
        }
    }

    // ---- write logits (+bias) to smem (alias stage buffers) ----
    __syncthreads();
    #pragma unroll
    for (int m = 0; m < 2; ++m) {
        const int r0 = wm * 32 + m * 16 + g;
        #pragma unroll
        for (int n = 0; n < 4; ++n) {
            const int c0 = wn * 32 + n * 8 + 2 * c;
            *(float2*)&ls[(size_t)r0 * LSTR + c0] =
                make_float2(acc[m][n][0] + sbias[c0], acc[m][n][1] + sbias[c0 + 1]);
            *(float2*)&ls[(size_t)(r0 + 8) * LSTR + c0] =
                make_float2(acc[m][n][2] + sbias[c0], acc[m][n][3] + sbias[c0 + 1]);
        }
    }
    __syncthreads();

    // ---- softmax + gather: 4 lanes per row (64 rows, 256 threads) ----
    const int r = tid >> 2;
    const int q = tid & 3;
    const float* lr2 = &ls[(size_t)r * LSTR];

    float mx = -3.0e38f;
    #pragma unroll
    for (int i = 0; i < 32; ++i) mx = fmaxf(mx, lr2[q + 4 * i]);
    mx = fmaxf(mx, __shfl_xor_sync(0xffffffffu, mx, 1));
    mx = fmaxf(mx, __shfl_xor_sync(0xffffffffu, mx, 2));

    float se = 0.f;
    #pragma unroll
    for (int i = 0; i < 32; ++i) se += __expf(lr2[q + 4 * i] - mx);
    se += __shfl_xor_sync(0xffffffffu, se, 1);
    se += __shfl_xor_sync(0xffffffffu, se, 2);

    float gg = 0.f;
    const int* dip = di + (size_t)(row0 + r) * 12;
    const int* dmp = dm + (size_t)(row0 + r) * 12;
    #pragma unroll
    for (int j = q; j < 12; j += 4) {
        int idx = dip[j];
        if (dmp[j]) gg += __expf(lr2[idx] - mx);
    }
    gg += __shfl_xor_sync(0xffffffffu, gg, 1);
    gg += __shfl_xor_sync(0xffffffffu, gg, 2);

    float part = (q == 0) ? (gg / se) : 0.f;

    // deterministic block reduce (8 warps)
    #pragma unroll
    for (int o = 16; o; o >>= 1) part += __shfl_down_sync(0xffffffffu, part, o);
    if (lane == 0) sred[wid] = part;
    __syncthreads();
    if (tid == 0) {
        float s = 0.f;
        #pragma unroll
        for (int i = 0; i < 8; ++i) s += sred[i];
        g_partials[bid] = s;
        __threadfence();
        unsigned old = atomicInc(&g_done, NCTA - 1);   // wraps to 0: replay-safe
        sflag[0] = (old == NCTA - 1) ? 1 : 0;
    }
    __syncthreads();

    // ---- fused finalize: WARP 0 of the last CTA only (no cross-warp smem) ----
    if (sflag[0] && wid == 0) {
        __threadfence();   // acquire all CTAs' g_partials
        float v = 0.f;
        #pragma unroll
        for (int i = 0; i < 8; ++i) v += g_partials[lane + 32 * i];
        #pragma unroll
        for (int o = 16; o; o >>= 1) v += __shfl_down_sync(0xffffffffu, v, o);
        if (lane == 0) out[0] = v * (1.0f / 65536.f);   // / (B * V)
    }
}

extern "C" void kernel_launch(void* const* d_in, const int* in_sizes, int n_in,
                              void* d_out, int out_size) {
    const float* X  = (const float*)d_in[0];
    const float* W  = (const float*)d_in[1];
    const float* b  = (const float*)d_in[2];
    const int*   di = (const int*)d_in[3];
    const int*   dm = (const int*)d_in[4];

    cudaFuncSetAttribute(qrl_h16_kernel,
                         cudaFuncAttributeMaxDynamicSharedMemorySize, SMEM_DYN);
    qrl_h16_kernel<<<NCTA, THREADS, SMEM_DYN>>>(X, W, b, di, dm, (float*)d_out);
}

// round 9
// speedup vs baseline: 1.4312x; 1.1309x over previous
#include <cuda_runtime.h>
#include <cuda_fp16.h>
#include <cstdint>

#define BATCH 16384
#define DIM   1024
#define TT    128
#define BM    64
#define NCTA  256
#define THREADS 256
#define KC    32
#define NCHUNK 32
#define NSTAGE 4
#define ABYTES 8192                   // 64 rows x 128B (f32)
#define BBYTES 16384                  // 128 rows x 128B (f32)
#define STAGE_BYTES 24576             // A + B
#define LSTR  130
#define MISC_OFF (NSTAGE*STAGE_BYTES) // 98304 (logits 64*130*4=33280 alias below)
#define SMEM_DYN (MISC_OFF + 1024)

__device__ float g_partials[NCTA];
__device__ unsigned int g_done = 0;   // self-resets via atomicInc wrap

// ---------------- PTX helpers ----------------
__device__ __forceinline__ uint32_t smem_u32(const void* p) {
    uint32_t a;
    asm("{ .reg .u64 t; cvta.to.shared.u64 t, %1; cvt.u32.u64 %0, t; }"
        : "=r"(a) : "l"(p));
    return a;
}
__device__ __forceinline__ void cp16(uint32_t saddr, const void* gaddr) {
    asm volatile("cp.async.cg.shared.global [%0], [%1], 16;"
                 :: "r"(saddr), "l"(gaddr) : "memory");
}
template <int IMM>
__device__ __forceinline__ uint4 lds128(uint32_t base) {
    uint4 v;
    asm volatile("ld.shared.v4.b32 {%0,%1,%2,%3}, [%4+%5];"
                 : "=r"(v.x), "=r"(v.y), "=r"(v.z), "=r"(v.w)
                 : "r"(base), "n"(IMM));
    return v;
}
__device__ __forceinline__ uint32_t cvt2(uint32_t x, uint32_t y) {
    __half2 h = __floats2half2_rn(__uint_as_float(x), __uint_as_float(y));
    return *(uint32_t*)&h;
}
__device__ __forceinline__ void mma_f16(float d[4],
                                        uint32_t a0, uint32_t a1, uint32_t a2, uint32_t a3,
                                        uint32_t b0, uint32_t b1) {
    asm volatile(
        "mma.sync.aligned.m16n8k16.row.col.f32.f16.f16.f32 "
        "{%0,%1,%2,%3}, {%4,%5,%6,%7}, {%8,%9}, {%0,%1,%2,%3};"
        : "+f"(d[0]), "+f"(d[1]), "+f"(d[2]), "+f"(d[3])
        : "r"(a0), "r"(a1), "r"(a2), "r"(a3), "r"(b0), "r"(b1));
}

// ---------------- fused kernel ----------------
__global__ __launch_bounds__(THREADS, 2)
void qrl_cp_kernel(const float* __restrict__ X,     // [B, D]
                   const float* __restrict__ W,     // [T, D]
                   const float* __restrict__ bias,  // [T]
                   const int*   __restrict__ di,    // [B, 12]
                   const int*   __restrict__ dm,    // [B, 12]
                   float* __restrict__ out)
{
    extern __shared__ __align__(128) char smem[];
    float* ls    = (float*)smem;                     // logits alias stage buffers post-GEMM
    float* sbias = (float*)(smem + MISC_OFF);        // 128 floats
    float* sred  = (float*)(smem + MISC_OFF + 512);  // 8 floats
    int*   sflag = (int*)  (smem + MISC_OFF + 576);

    const uint32_t sbase = smem_u32(smem);
    const int tid  = threadIdx.x;
    const int wid  = tid >> 5;
    const int lane = tid & 31;
    const int bid  = blockIdx.x;
    const int row0 = bid * BM;

    const int wm = wid & 1;        // 2 m-groups of 32 rows
    const int wn = wid >> 1;       // 4 n-groups of 32 cols
    const int g  = lane >> 2;      // 0..7
    const int c  = lane & 3;       // 0..3

    if (tid < TT) sbias[tid] = bias[tid];

    // fragment unit offsets: physical unit (s*4+c) swizzled by row parity (row&1 == g&1)
    const uint32_t off0 = 16u * ((uint32_t)c ^ (((uint32_t)g & 1u) << 2));
    const uint32_t off1 = off0 ^ 64u;
    const uint32_t arow = (uint32_t)((wm * 32 + g) * 128);
    const uint32_t brow = (uint32_t)(ABYTES + (wn * 32 + g) * 128);

    // ---- cp.async loader geometry: thread -> (row tid>>3, 16B unit tid&7) ----
    const int lr0 = tid >> 3;      // 0..31
    const int lun = tid & 7;
    const uint32_t lsw = 16u * ((uint32_t)lun ^ (((uint32_t)lr0 & 1u) << 2));
    const uint32_t dA0 = (uint32_t)(lr0 * 128) + lsw;             // A rows lr0, lr0+32
    const uint32_t dB0 = (uint32_t)(ABYTES + lr0 * 128) + lsw;    // B rows lr0 + 32i
    const float* sx = X + (size_t)(row0 + lr0) * DIM + lun * 4;
    const float* sw_ = W + (size_t)lr0 * DIM + lun * 4;

    auto load_chunk = [&](int kc, int st) {
        const uint32_t sa = sbase + st * STAGE_BYTES;
        const float* x = sx + kc * KC;
        cp16(sa + dA0,        x);
        cp16(sa + dA0 + 4096, x + (size_t)32 * DIM);
        const float* w = sw_ + kc * KC;
        #pragma unroll
        for (int i = 0; i < 4; ++i)
            cp16(sa + dB0 + i * 4096, w + (size_t)i * 32 * DIM);
        asm volatile("cp.async.commit_group;" ::: "memory");
    };

    float acc[2][4][4];
    #pragma unroll
    for (int m = 0; m < 2; ++m)
        #pragma unroll
        for (int n = 0; n < 4; ++n)
            #pragma unroll
            for (int q = 0; q < 4; ++q) acc[m][n][q] = 0.f;

    load_chunk(0, 0);
    load_chunk(1, 1);
    load_chunk(2, 2);

    for (int kc = 0; kc < NCHUNK; ++kc) {
        if (kc < NCHUNK - 2)      asm volatile("cp.async.wait_group 2;" ::: "memory");
        else if (kc == NCHUNK - 2) asm volatile("cp.async.wait_group 1;" ::: "memory");
        else                      asm volatile("cp.async.wait_group 0;" ::: "memory");
        __syncthreads();
        if (kc + 3 < NCHUNK) load_chunk(kc + 3, (kc + 3) & (NSTAGE - 1));

        const uint32_t sa = sbase + (kc & (NSTAGE - 1)) * STAGE_BYTES;
        const uint32_t bA0 = sa + arow + off0, bA1 = sa + arow + off1;
        const uint32_t bB0 = sa + brow + off0, bB1 = sa + brow + off1;

        #pragma unroll
        for (int s = 0; s < 2; ++s) {
            const uint32_t aA = s ? bA1 : bA0;
            const uint32_t aB = s ? bB1 : bB0;
            // A: m-tiles 0/1, each rows (g, g+8): 4 LDS.128
            uint4 A00 = lds128<0>(aA);       // m0 rows g
            uint4 A01 = lds128<1024>(aA);    // m0 rows g+8
            uint4 A10 = lds128<2048>(aA);    // m1 rows g+16
            uint4 A11 = lds128<3072>(aA);    // m1 rows g+24
            // B: 4 col-groups
            uint4 B0 = lds128<0>(aB);
            uint4 B1 = lds128<1024>(aB);
            uint4 B2 = lds128<2048>(aB);
            uint4 B3 = lds128<3072>(aB);

            uint32_t a0[2], a1[2], a2[2], a3[2];
            a0[0] = cvt2(A00.x, A00.y); a1[0] = cvt2(A01.x, A01.y);
            a2[0] = cvt2(A00.z, A00.w); a3[0] = cvt2(A01.z, A01.w);
            a0[1] = cvt2(A10.x, A10.y); a1[1] = cvt2(A11.x, A11.y);
            a2[1] = cvt2(A10.z, A10.w); a3[1] = cvt2(A11.z, A11.w);

            uint32_t b0[4], b1[4];
            b0[0] = cvt2(B0.x, B0.y); b1[0] = cvt2(B0.z, B0.w);
            b0[1] = cvt2(B1.x, B1.y); b1[1] = cvt2(B1.z, B1.w);
            b0[2] = cvt2(B2.x, B2.y); b1[2] = cvt2(B2.z, B2.w);
            b0[3] = cvt2(B3.x, B3.y); b1[3] = cvt2(B3.z, B3.w);

            #pragma unroll
            for (int m = 0; m < 2; ++m)
                #pragma unroll
                for (int n = 0; n < 4; ++n)
                    mma_f16(acc[m][n], a0[m], a1[m], a2[m], a3[m], b0[n], b1[n]);
        }
    }

    // ---- write logits (+bias) to smem (alias stage buffers) ----
    __syncthreads();
    #pragma unroll
    for (int m = 0; m < 2; ++m) {
        const int r0 = wm * 32 + m * 16 + g;
        #pragma unroll
        for (int n = 0; n < 4; ++n) {
            const int c0 = wn * 32 + n * 8 + 2 * c;
            *(float2*)&ls[(size_t)r0 * LSTR + c0] =
                make_float2(acc[m][n][0] + sbias[c0], acc[m][n][1] + sbias[c0 + 1]);
            *(float2*)&ls[(size_t)(r0 + 8) * LSTR + c0] =
                make_float2(acc[m][n][2] + sbias[c0], acc[m][n][3] + sbias[c0 + 1]);
        }
    }
    __syncthreads();

    // ---- softmax + gather: 4 lanes per row (64 rows, 256 threads) ----
    const int r = tid >> 2;
    const int q = tid & 3;
    const float* lr2 = &ls[(size_t)r * LSTR];

    float mx = -3.0e38f;
    #pragma unroll
    for (int i = 0; i < 32; ++i) mx = fmaxf(mx, lr2[q + 4 * i]);
    mx = fmaxf(mx, __shfl_xor_sync(0xffffffffu, mx, 1));
    mx = fmaxf(mx, __shfl_xor_sync(0xffffffffu, mx, 2));

    float se = 0.f;
    #pragma unroll
    for (int i = 0; i < 32; ++i) se += __expf(lr2[q + 4 * i] - mx);
    se += __shfl_xor_sync(0xffffffffu, se, 1);
    se += __shfl_xor_sync(0xffffffffu, se, 2);

    float gg = 0.f;
    const int* dip = di + (size_t)(row0 + r) * 12;
    const int* dmp = dm + (size_t)(row0 + r) * 12;
    #pragma unroll
    for (int j = q; j < 12; j += 4) {
        int idx = dip[j];
        if (dmp[j]) gg += __expf(lr2[idx] - mx);
    }
    gg += __shfl_xor_sync(0xffffffffu, gg, 1);
    gg += __shfl_xor_sync(0xffffffffu, gg, 2);

    float part = (q == 0) ? (gg / se) : 0.f;

    // deterministic block reduce (8 warps)
    #pragma unroll
    for (int o = 16; o; o >>= 1) part += __shfl_down_sync(0xffffffffu, part, o);
    if (lane == 0) sred[wid] = part;
    __syncthreads();
    if (tid == 0) {
        float s = 0.f;
        #pragma unroll
        for (int i = 0; i < 8; ++i) s += sred[i];
        g_partials[bid] = s;
        __threadfence();
        unsigned old = atomicInc(&g_done, NCTA - 1);   // wraps to 0: replay-safe
        sflag[0] = (old == NCTA - 1) ? 1 : 0;
    }
    __syncthreads();

    // ---- fused finalize: WARP 0 of the last CTA only (no cross-warp smem) ----
    if (sflag[0] && wid == 0) {
        __threadfence();   // acquire all CTAs' g_partials
        float v = 0.f;
        #pragma unroll
        for (int i = 0; i < 8; ++i) v += g_partials[lane + 32 * i];
        #pragma unroll
        for (int o = 16; o; o >>= 1) v += __shfl_down_sync(0xffffffffu, v, o);
        if (lane == 0) out[0] = v * (1.0f / 65536.f);   // / (B * V)
    }
}

extern "C" void kernel_launch(void* const* d_in, const int* in_sizes, int n_in,
                              void* d_out, int out_size) {
    const float* X  = (const float*)d_in[0];
    const float* W  = (const float*)d_in[1];
    const float* b  = (const float*)d_in[2];
    const int*   di = (const int*)d_in[3];
    const int*   dm = (const int*)d_in[4];

    cudaFuncSetAttribute(qrl_cp_kernel,
                         cudaFuncAttributeMaxDynamicSharedMemorySize, SMEM_DYN);
    qrl_cp_kernel<<<NCTA, THREADS, SMEM_DYN>>>(X, W, b, di, dm, (float*)d_out);
}

// round 10
// speedup vs baseline: 1.6181x; 1.1306x over previous
#include <cuda_runtime.h>
#include <cuda_fp16.h>
#include <cstdint>

#define BATCH 16384
#define DIM   1024
#define TT    128
#define BM    64
#define NCTA  256
#define THREADS 256
#define KC    32
#define NCHUNK 32
#define NSTAGE 4
#define ABYTES 8192                   // A: 64 rows x 128B (f32)
#define BOFF   8192
#define BBYTES 8192                   // B: 128 rows x 64B (f16)
#define STAGE_BYTES 16384             // A + B
#define LSTR  130
#define MISC_OFF (NSTAGE*STAGE_BYTES) // 65536 (logits 64*130*4=33280 alias below)
#define SMEM_DYN (MISC_OFF + 1024)

__device__ float g_partials[NCTA];
__device__ unsigned int g_done = 0;     // self-resets via atomicInc wrap
__device__ __align__(16) __half g_W16[TT * DIM];   // pre-converted, k-permuted W

// ---------------- PTX helpers ----------------
__device__ __forceinline__ uint32_t smem_u32(const void* p) {
    uint32_t a;
    asm("{ .reg .u64 t; cvta.to.shared.u64 t, %1; cvt.u32.u64 %0, t; }"
        : "=r"(a) : "l"(p));
    return a;
}
__device__ __forceinline__ void cp16(uint32_t saddr, const void* gaddr) {
    asm volatile("cp.async.cg.shared.global [%0], [%1], 16;"
                 :: "r"(saddr), "l"(gaddr) : "memory");
}
template <int IMM>
__device__ __forceinline__ uint4 lds128(uint32_t base) {
    uint4 v;
    asm volatile("ld.shared.v4.b32 {%0,%1,%2,%3}, [%4+%5];"
                 : "=r"(v.x), "=r"(v.y), "=r"(v.z), "=r"(v.w)
                 : "r"(base), "n"(IMM));
    return v;
}
__device__ __forceinline__ uint32_t cvt2(uint32_t x, uint32_t y) {
    __half2 h = __floats2half2_rn(__uint_as_float(x), __uint_as_float(y));
    return *(uint32_t*)&h;
}
__device__ __forceinline__ void mma_f16(float d[4],
                                        uint32_t a0, uint32_t a1, uint32_t a2, uint32_t a3,
                                        uint32_t b0, uint32_t b1) {
    asm volatile(
        "mma.sync.aligned.m16n8k16.row.col.f32.f16.f16.f32 "
        "{%0,%1,%2,%3}, {%4,%5,%6,%7}, {%8,%9}, {%0,%1,%2,%3};"
        : "+f"(d[0]), "+f"(d[1]), "+f"(d[2]), "+f"(d[3])
        : "r"(a0), "r"(a1), "r"(a2), "r"(a3), "r"(b0), "r"(b1));
}

// ---------------- prepass: W f32 -> f16, k-permuted ----------------
// unit (t, kc, u): 8 halfs; j<4 -> phys k = kc*32+4u+j ; j>=4 -> kc*32+16+4u+(j-4)
__global__ void qrl_wconv_kernel(const float* __restrict__ W) {
    int uidx = blockIdx.x * blockDim.x + threadIdx.x;   // 0..16383
    int u  = uidx & 3;
    int kc = (uidx >> 2) & 31;
    int t  = uidx >> 7;
    const float* src = W + (size_t)t * DIM + kc * 32 + 4 * u;
    float4 lo = *(const float4*)src;          // phys 4u..4u+3
    float4 hi = *(const float4*)(src + 16);   // phys 16+4u..+3
    uint4 v;
    v.x = cvt2(__float_as_uint(lo.x), __float_as_uint(lo.y));
    v.y = cvt2(__float_as_uint(lo.z), __float_as_uint(lo.w));
    v.z = cvt2(__float_as_uint(hi.x), __float_as_uint(hi.y));
    v.w = cvt2(__float_as_uint(hi.z), __float_as_uint(hi.w));
    *(uint4*)(g_W16 + (size_t)uidx * 8) = v;
}

// ---------------- fused main kernel ----------------
__global__ __launch_bounds__(THREADS, 2)
void qrl_cp_kernel(const float* __restrict__ X,     // [B, D]
                   const float* __restrict__ bias,  // [T]
                   const int*   __restrict__ di,    // [B, 12]
                   const int*   __restrict__ dm,    // [B, 12]
                   float* __restrict__ out)
{
    extern __shared__ __align__(128) char smem[];
    float* ls    = (float*)smem;                     // logits alias stage buffers post-GEMM
    float* sbias = (float*)(smem + MISC_OFF);        // 128 floats
    float* sred  = (float*)(smem + MISC_OFF + 512);  // 8 floats
    int*   sflag = (int*)  (smem + MISC_OFF + 576);

    const uint32_t sbase = smem_u32(smem);
    const int tid  = threadIdx.x;
    const int wid  = tid >> 5;
    const int lane = tid & 31;
    const int bid  = blockIdx.x;
    const int row0 = bid * BM;

    const int wm = wid & 1;        // 2 m-groups of 32 rows
    const int wn = wid >> 1;       // 4 n-groups of 32 cols
    const int g  = lane >> 2;      // 0..7
    const int c  = lane & 3;       // 0..3

    if (tid < TT) sbias[tid] = bias[tid];

    // A fragment offsets: f32, parity swizzle (row&1 == g&1)
    const uint32_t offA0 = 16u * ((uint32_t)c ^ (((uint32_t)g & 1u) << 2));
    const uint32_t offA1 = offA0 ^ 64u;
    const uint32_t arow  = (uint32_t)((wm * 32 + g) * 128);
    // B fragment offset: f16 rows (64B), bit-1-of-row swizzle (row&2 == g&2)
    const uint32_t brow  = (uint32_t)(BOFF + (wn * 32 + g) * 64
                                      + (((uint32_t)c ^ ((uint32_t)g & 2u)) * 16));

    // ---- A loader: thread -> (row tid>>3, unit tid&7), rows lr0 / lr0+32 ----
    const int lr0 = tid >> 3;
    const int lun = tid & 7;
    const uint32_t dA0 = (uint32_t)(lr0 * 128)
                       + 16u * ((uint32_t)lun ^ (((uint32_t)lr0 & 1u) << 2));
    const float* sx = X + (size_t)(row0 + lr0) * DIM + lun * 4;
    // ---- B loader: thread -> (row tid>>2, unit tid&3), rows br0 / br0+64 ----
    const int br0 = tid >> 2;
    const int bun = tid & 3;
    const uint32_t dB0 = (uint32_t)(BOFF + br0 * 64)
                       + 16u * ((uint32_t)bun ^ ((uint32_t)br0 & 2u));
    const __half* sw0 = g_W16 + (size_t)br0 * DIM + bun * 8;   // permuted layout

    auto load_chunk = [&](int kc, int st) {
        const uint32_t sa = sbase + st * STAGE_BYTES;
        const float* x = sx + kc * KC;
        cp16(sa + dA0,        x);
        cp16(sa + dA0 + 4096, x + (size_t)32 * DIM);
        const __half* w = sw0 + kc * KC;
        cp16(sa + dB0,        w);
        cp16(sa + dB0 + 4096, w + (size_t)64 * DIM);   // rows +64
        asm volatile("cp.async.commit_group;" ::: "memory");
    };

    float acc[2][4][4];
    #pragma unroll
    for (int m = 0; m < 2; ++m)
        #pragma unroll
        for (int n = 0; n < 4; ++n)
            #pragma unroll
            for (int q = 0; q < 4; ++q) acc[m][n][q] = 0.f;

    load_chunk(0, 0);
    load_chunk(1, 1);
    load_chunk(2, 2);

    for (int kc = 0; kc < NCHUNK; ++kc) {
        if (kc < NCHUNK - 2)       asm volatile("cp.async.wait_group 2;" ::: "memory");
        else if (kc == NCHUNK - 2) asm volatile("cp.async.wait_group 1;" ::: "memory");
        else                       asm volatile("cp.async.wait_group 0;" ::: "memory");
        __syncthreads();
        if (kc + 3 < NCHUNK) load_chunk(kc + 3, (kc + 3) & (NSTAGE - 1));

        const uint32_t sa = sbase + (kc & (NSTAGE - 1)) * STAGE_BYTES;

        // B: one LDS.128 per col-group covers both k16 substeps (.xy / .zw)
        const uint32_t aB = sa + brow;
        uint4 Bf[4];
        Bf[0] = lds128<0>(aB);        // cols wn*32+g
        Bf[1] = lds128<512>(aB);      // +8
        Bf[2] = lds128<1024>(aB);     // +16
        Bf[3] = lds128<1536>(aB);     // +24

        #pragma unroll
        for (int s = 0; s < 2; ++s) {
            const uint32_t aA = sa + arow + (s ? offA1 : offA0);
            uint4 A00 = lds128<0>(aA);       // m0 rows g
            uint4 A01 = lds128<1024>(aA);    // m0 rows g+8
            uint4 A10 = lds128<2048>(aA);    // m1 rows g+16
            uint4 A11 = lds128<3072>(aA);    // m1 rows g+24

            uint32_t a0[2], a1[2], a2[2], a3[2];
            a0[0] = cvt2(A00.x, A00.y); a1[0] = cvt2(A01.x, A01.y);
            a2[0] = cvt2(A00.z, A00.w); a3[0] = cvt2(A01.z, A01.w);
            a0[1] = cvt2(A10.x, A10.y); a1[1] = cvt2(A11.x, A11.y);
            a2[1] = cvt2(A10.z, A10.w); a3[1] = cvt2(A11.z, A11.w);

            #pragma unroll
            for (int m = 0; m < 2; ++m)
                #pragma unroll
                for (int n = 0; n < 4; ++n)
                    mma_f16(acc[m][n], a0[m], a1[m], a2[m], a3[m],
                            s ? Bf[n].z : Bf[n].x, s ? Bf[n].w : Bf[n].y);
        }
    }

    // ---- write logits (+bias) to smem (alias stage buffers) ----
    __syncthreads();
    #pragma unroll
    for (int m = 0; m < 2; ++m) {
        const int r0 = wm * 32 + m * 16 + g;
        #pragma unroll
        for (int n = 0; n < 4; ++n) {
            const int c0 = wn * 32 + n * 8 + 2 * c;
            *(float2*)&ls[(size_t)r0 * LSTR + c0] =
                make_float2(acc[m][n][0] + sbias[c0], acc[m][n][1] + sbias[c0 + 1]);
            *(float2*)&ls[(size_t)(r0 + 8) * LSTR + c0] =
                make_float2(acc[m][n][2] + sbias[c0], acc[m][n][3] + sbias[c0 + 1]);
        }
    }
    __syncthreads();

    // ---- softmax + gather: 4 lanes per row (64 rows, 256 threads) ----
    const int r = tid >> 2;
    const int q = tid & 3;
    const float* lr2 = &ls[(size_t)r * LSTR];

    float mx = -3.0e38f;
    #pragma unroll
    for (int i = 0; i < 32; ++i) mx = fmaxf(mx, lr2[q + 4 * i]);
    mx = fmaxf(mx, __shfl_xor_sync(0xffffffffu, mx, 1));
    mx = fmaxf(mx, __shfl_xor_sync(0xffffffffu, mx, 2));

    float se = 0.f;
    #pragma unroll
    for (int i = 0; i < 32; ++i) se += __expf(lr2[q + 4 * i] - mx);
    se += __shfl_xor_sync(0xffffffffu, se, 1);
    se += __shfl_xor_sync(0xffffffffu, se, 2);

    float gg = 0.f;
    const int* dip = di + (size_t)(row0 + r) * 12;
    const int* dmp = dm + (size_t)(row0 + r) * 12;
    #pragma unroll
    for (int j = q; j < 12; j += 4) {
        int idx = dip[j];
        if (dmp[j]) gg += __expf(lr2[idx] - mx);
    }
    gg += __shfl_xor_sync(0xffffffffu, gg, 1);
    gg += __shfl_xor_sync(0xffffffffu, gg, 2);

    float part = (q == 0) ? (gg / se) : 0.f;

    // deterministic block reduce (8 warps)
    #pragma unroll
    for (int o = 16; o; o >>= 1) part += __shfl_down_sync(0xffffffffu, part, o);
    if (lane == 0) sred[wid] = part;
    __syncthreads();
    if (tid == 0) {
        float s = 0.f;
        #pragma unroll
        for (int i = 0; i < 8; ++i) s += sred[i];
        g_partials[bid] = s;
        __threadfence();
        unsigned old = atomicInc(&g_done, NCTA - 1);   // wraps to 0: replay-safe
        sflag[0] = (old == NCTA - 1) ? 1 : 0;
    }
    __syncthreads();

    // ---- fused finalize: WARP 0 of the last CTA only ----
    if (sflag[0] && wid == 0) {
        __threadfence();   // acquire all CTAs' g_partials
        float v = 0.f;
        #pragma unroll
        for (int i = 0; i < 8; ++i) v += g_partials[lane + 32 * i];
        #pragma unroll
        for (int o = 16; o; o >>= 1) v += __shfl_down_sync(0xffffffffu, v, o);
        if (lane == 0) out[0] = v * (1.0f / 65536.f);   // / (B * V)
    }
}

extern "C" void kernel_launch(void* const* d_in, const int* in_sizes, int n_in,
                              void* d_out, int out_size) {
    const float* X  = (const float*)d_in[0];
    const float* W  = (const float*)d_in[1];
    const float* b  = (const float*)d_in[2];
    const int*   di = (const int*)d_in[3];
    const int*   dm = (const int*)d_in[4];

    qrl_wconv_kernel<<<64, 256>>>(W);   // ~0.2us: W f32 -> permuted f16
    cudaFuncSetAttribute(qrl_cp_kernel,
                         cudaFuncAttributeMaxDynamicSharedMemorySize, SMEM_DYN);
    qrl_cp_kernel<<<NCTA, THREADS, SMEM_DYN>>>(X, b, di, dm, (float*)d_out);
}